// round 10
// baseline (speedup 1.0000x reference)
#include <cuda_runtime.h>

// HMM forward: alpha_t = (alpha_{t-1} @ A) * B[:, obs_t],  out = sum(alpha_{T-1})
// R10 = R6 core (tagged 8B alpha elements, one 128B publish line per block,
// quarter barriers, packed fp32x2 FMA) with the pair named-barrier replaced by
// a direct SMEM release/acquire handoff:
//   poller: store packed half-partials + release tag, then spin on 'done'
//           (poll restart strictly AFTER own-block publish -> quiet lines
//           during the chip-wide publish window; R9 showed early polling hurts)
//   epi:    acquire-spin on tag (no barrier wake), combine, publish, release done.

namespace {
constexpr int GRID = 128;
constexpr int NT   = 256;
constexpr int S    = 2048;
constexpr int V    = 32768;
constexpr int T    = 4096;
constexpr int NCOL = 16;      // columns per block
}

typedef unsigned long long u64;

// Each uint4 = two elements: (val0, tag0, val1, tag1). 3 rotating buffers.
__device__ uint4    g_alpha3[3][S / 2];
__device__ unsigned g_epoch = 0;
__device__ unsigned g_done  = 0;

__device__ __forceinline__ uint4 ld_vol4(const uint4* p) {
    uint4 v;
    asm volatile("ld.volatile.global.v4.u32 {%0,%1,%2,%3}, [%4];"
                 : "=r"(v.x), "=r"(v.y), "=r"(v.z), "=r"(v.w) : "l"(p) : "memory");
    return v;
}
__device__ __forceinline__ void st_cg_v2(void* p, unsigned a, unsigned b) {
    asm volatile("st.global.cg.v2.u32 [%0], {%1,%2};" :: "l"(p), "r"(a), "r"(b) : "memory");
}
__device__ __forceinline__ unsigned ld_acq_cta(const unsigned* p) {
    unsigned v;
    asm volatile("ld.acquire.cta.b32 %0, [%1];" : "=r"(v) : "l"(p) : "memory");
    return v;
}
__device__ __forceinline__ void st_rel_cta(unsigned* p, unsigned v) {
    asm volatile("st.release.cta.b32 [%0], %1;" :: "l"(p), "r"(v) : "memory");
}
__device__ __forceinline__ u64 pack2(float a, float b) {
    u64 d;
    asm("mov.b64 %0, {%1,%2};" : "=l"(d) : "f"(a), "f"(b));
    return d;
}
__device__ __forceinline__ u64 fma2(u64 a, u64 b, u64 c) {
    u64 d;
    asm("fma.rn.f32x2 %0, %1, %2, %3;" : "=l"(d) : "l"(a), "l"(b), "l"(c));
    return d;
}
__device__ __forceinline__ u64 add2(u64 a, u64 b) {
    u64 d;
    asm("add.rn.f32x2 %0, %1, %2;" : "=l"(d) : "l"(a), "l"(b));
    return d;
}

__global__ void __launch_bounds__(NT, 1) hmm_forward_kernel(
    const int*   __restrict__ obs,
    const float* __restrict__ A,
    const float* __restrict__ B,
    const float* __restrict__ pi,
    float*       __restrict__ out)
{
    __shared__ __align__(16) float alpha_sm[2][2][1024]; // [parity][half][elem]
    __shared__ __align__(16) u64   pairbuf[2][4][2];     // [parity][pair(cg)][acc01,acc23]
    __shared__ unsigned ptag [2][4];                     // partner-partial ready tag
    __shared__ unsigned pdone[2][4];                     // publish-done tag

    const int tid  = threadIdx.x;
    const int blk  = blockIdx.x;
    const int w    = tid >> 5;
    const int lane = tid & 31;
    const int cg   = w & 3;               // column group / pair id 0..3
    const int rg   = w >> 2;              // row group 0..1 (half = 1024 rows)
    const int jb   = blk * NCOL + cg * 4; // first of this warp's 4 columns

    // Pollers: w2 (h0 qA: chunks 0-7), w3 (h0 qB: 8-15), w4 (h1 qA), w5 (h1 qB).
    const bool is_poller = (w >= 2) && (w <= 5);
    const int  poll_half = (w <= 3) ? 0 : 1;
    const int  chunk_off = (w == 2 || w == 4) ? 0 : 8;
    const bool is_qA     = (w == 2 || w == 4);
    // Quarter barriers: half0 -> bars 1(qA),2(qB); half1 -> bars 3(qA),4(qB).
    const int  barA = 1 + rg * 2;
    const int  barB = 2 + rg * 2;
    // Epilogue warp per pair: pair0->w0, pair1->w1, pair2->w6, pair3->w7.
    const bool is_epi = !is_poller;

    // Readers initialize the tags they will spin on (replay-safe: spin targets
    // are epoch-unique and never 0). Writers first touch these thousands of
    // cycles later (after A-tile load + step-1 detect + FMA).
    if (lane == 0) {
        if (is_epi)    { ptag [0][cg] = 0u; ptag [1][cg] = 0u; }
        if (is_poller) { pdone[0][cg] = 0u; pdone[1][cg] = 0u; }
    }

    // ---- Load A tile into packed-pair registers (one time) ----
    // Thread covers rows rg*1024 + 4*lane + 128*k + rr (k<8, rr<4), cols jb..jb+3.
    u64 areg_lo[8][4], areg_hi[8][4];
#pragma unroll
    for (int k = 0; k < 8; k++) {
#pragma unroll
        for (int rr = 0; rr < 4; rr++) {
            int row = rg * 1024 + 4 * lane + 128 * k + rr;
            float4 a4 = *reinterpret_cast<const float4*>(&A[(size_t)row * S + jb]);
            areg_lo[k][rr] = pack2(a4.x, a4.y);
            areg_hi[k][rr] = pack2(a4.z, a4.w);
        }
    }

    const unsigned epoch = *(volatile unsigned*)&g_epoch;
    const unsigned tagbase = epoch * 4096u + 1u;   // >0, unique across replays

    if (blk == 0 && tid == 0) *out = 0.0f;

    // ---- Publish alpha_0 = pi * B[:, obs[0]] with tag(0) ----
    if (is_epi && lane < 4) {
        int   c  = jb + lane;
        int   o0 = __ldg(&obs[0]);
        float v  = pi[c] * __ldg(&B[(size_t)c * V + o0]);
        st_cg_v2(reinterpret_cast<char*>(g_alpha3[0]) + (size_t)c * 8,
                 __float_as_uint(v), tagbase);
    }

    for (int s = 1; s < T; s++) {
        const int      par  = s & 1;
        const int      bufR = (s - 1) % 3;
        const int      bufW = s % 3;
        const unsigned tagR = tagbase + (unsigned)(s - 1);
        const unsigned tagW = tagbase + (unsigned)s;

        // Epilogue lanes prefetch their emission factor (independent of alpha).
        float bj = 0.0f;
        if (is_epi && lane < 4) {
            int o = __ldg(&obs[s]);
            bj = __ldg(&B[(size_t)(jb + lane) * V + o]);
        }

        // ---- Pollers: wait for this quarter's 8 chunks, restripe to SMEM ----
        if (is_poller) {
            const uint4* base = &g_alpha3[bufR][poll_half * 512] + chunk_off * 32 + lane;
            uint4 v[8];
            for (;;) {
                bool ok = true;
#pragma unroll
                for (int c = 0; c < 8; c++) {
                    v[c] = ld_vol4(base + c * 32);
                    ok &= (v[c].y == tagR) & (v[c].w == tagR);
                }
                if (__all_sync(0xffffffffu, ok)) break;
            }
#pragma unroll
            for (int c = 0; c < 8; c++) {
                float2 f = make_float2(__uint_as_float(v[c].x), __uint_as_float(v[c].z));
                *reinterpret_cast<float2*>(
                    &alpha_sm[par][poll_half][(chunk_off + c) * 64 + 2 * lane]) = f;
            }
            // Publish my quarter to the other 3 warps of this half.
            if (is_qA) asm volatile("bar.arrive %0, 128;" :: "r"(barA) : "memory");
            else       asm volatile("bar.arrive %0, 128;" :: "r"(barB) : "memory");
        }

        const float4* sm4 = reinterpret_cast<const float4*>(alpha_sm[par][rg]);
        u64 acc01 = 0, acc23 = 0;   // packed (col0,col1), (col2,col3)

        // Quarter A (k=0..3): qA poller has its own data; others sync.
        if (!(is_poller && is_qA))
            asm volatile("bar.sync %0, 128;" :: "r"(barA) : "memory");
#pragma unroll
        for (int k = 0; k < 4; k++) {
            float4 av = sm4[k * 32 + lane];
            u64 ax = pack2(av.x, av.x), ay = pack2(av.y, av.y);
            u64 az = pack2(av.z, av.z), aw = pack2(av.w, av.w);
            acc01 = fma2(ax, areg_lo[k][0], acc01);
            acc23 = fma2(ax, areg_hi[k][0], acc23);
            acc01 = fma2(ay, areg_lo[k][1], acc01);
            acc23 = fma2(ay, areg_hi[k][1], acc23);
            acc01 = fma2(az, areg_lo[k][2], acc01);
            acc23 = fma2(az, areg_hi[k][2], acc23);
            acc01 = fma2(aw, areg_lo[k][3], acc01);
            acc23 = fma2(aw, areg_hi[k][3], acc23);
        }
        // Quarter B (k=4..7): qB poller already has its data.
        if (!(is_poller && !is_qA))
            asm volatile("bar.sync %0, 128;" :: "r"(barB) : "memory");
#pragma unroll
        for (int k = 4; k < 8; k++) {
            float4 av = sm4[k * 32 + lane];
            u64 ax = pack2(av.x, av.x), ay = pack2(av.y, av.y);
            u64 az = pack2(av.z, av.z), aw = pack2(av.w, av.w);
            acc01 = fma2(ax, areg_lo[k][0], acc01);
            acc23 = fma2(ax, areg_hi[k][0], acc23);
            acc01 = fma2(ay, areg_lo[k][1], acc01);
            acc23 = fma2(ay, areg_hi[k][1], acc23);
            acc01 = fma2(az, areg_lo[k][2], acc01);
            acc23 = fma2(az, areg_hi[k][2], acc23);
            acc01 = fma2(aw, areg_lo[k][3], acc01);
            acc23 = fma2(aw, areg_hi[k][3], acc23);
        }

        // Warp xor-reduce: every lane ends with this half's column totals.
#pragma unroll
        for (int off = 16; off > 0; off >>= 1) {
            acc01 = add2(acc01, __shfl_xor_sync(0xffffffffu, acc01, off));
            acc23 = add2(acc23, __shfl_xor_sync(0xffffffffu, acc23, off));
        }

        if (is_poller) {
            // Hand packed half-partials to the pair's epilogue warp.
            if (lane == 0) {
                pairbuf[par][cg][0] = acc01;
                pairbuf[par][cg][1] = acc23;
                st_rel_cta(&ptag[par][cg], tagW);  // release: orders pairbuf
            }
            // Throttle: restart polling only AFTER own-block publish, keeping
            // the alpha lines quiet during the chip-wide publish window.
            if (s != T - 1) {
                const unsigned* dp = &pdone[par][cg];
                while (ld_acq_cta(dp) != tagW) { }
            }
        } else {
            // Epilogue: acquire partner's partials (no barrier wake).
            const unsigned* tp = &ptag[par][cg];
            while (ld_acq_cta(tp) != tagW) { }
            u64 p01 = pairbuf[par][cg][0];
            u64 p23 = pairbuf[par][cg][1];
            u64 s01 = add2(acc01, p01);
            u64 s23 = add2(acc23, p23);

            u64 sel = (lane & 2) ? s23 : s01;
            unsigned lo, hi;
            asm("mov.b64 {%0,%1}, %2;" : "=r"(lo), "=r"(hi) : "l"(sel));
            float pv = __uint_as_float((lane & 1) ? hi : lo) * bj;

            if (s == T - 1) {
                float t = (lane < 4) ? pv : 0.0f;
                t += __shfl_xor_sync(0xffffffffu, t, 1);
                t += __shfl_xor_sync(0xffffffffu, t, 2);
                if (lane == 0) {
                    atomicAdd(out, t);
                    unsigned d = atomicAdd(&g_done, 1u);
                    if (d == 4u * GRID - 1u) {
                        *(volatile unsigned*)&g_done  = 0u;
                        *(volatile unsigned*)&g_epoch = epoch + 1u;
                    }
                }
            } else {
                if (lane < 4) {
                    st_cg_v2(reinterpret_cast<char*>(&g_alpha3[bufW][0]) +
                                 (size_t)(jb + lane) * 8,
                             __float_as_uint(pv), tagW);
                }
                if (lane == 0) st_rel_cta(&pdone[par][cg], tagW);
            }
        }
        // alpha_sm parity-2 safety (unchanged from R6): a poller's step-(s+2)
        // restripe follows its step-(s+1) other-quarter bar.sync, whose release
        // requires every consumer warp's arrival there, which follows their
        // step-s reads. pairbuf/ptag/pdone are parity-2 and tag-guarded: the
        // done(s) handshake orders the next writer behind the reader.
    }
}

extern "C" void kernel_launch(void* const* d_in, const int* in_sizes, int n_in,
                              void* d_out, int out_size) {
    const int*   obs = (const int*)d_in[0];
    const float* A   = (const float*)d_in[1];
    const float* B   = (const float*)d_in[2];
    const float* pi  = (const float*)d_in[3];
    float*       out = (float*)d_out;
    (void)in_sizes; (void)n_in; (void)out_size;

    hmm_forward_kernel<<<GRID, NT>>>(obs, A, B, pi, out);
}